// round 4
// baseline (speedup 1.0000x reference)
#include <cuda_runtime.h>
#include <math.h>

#define BQ 32
#define CC 256
#define HH 64
#define WW 64
#define K9 (CC*9)          // 2304

// Scratch: conv1 output (only intermediate left; bn1 is fused into conv1).
__device__ float g_bufB[(size_t)BQ*CC*HH*WW];

// Packed dual-FMA: d.lo = a.lo*b.lo + c.lo ; d.hi = a.hi*b.hi + c.hi
__device__ __forceinline__ unsigned long long ffma2(unsigned long long a,
                                                    unsigned long long b,
                                                    unsigned long long c)
{
    asm("fma.rn.f32x2 %0, %1, %2, %0;" : "+l"(c) : "l"(a), "l"(b));
    return c;
}
__device__ __forceinline__ float lo32(unsigned long long v) {
    return __uint_as_float((unsigned)(v & 0xffffffffull));
}
__device__ __forceinline__ float hi32(unsigned long long v) {
    return __uint_as_float((unsigned)(v >> 32));
}

// ---------------------------------------------------------------------------
// Per-sample 3x3 conv (SAME, stride 1), weights synthesized on the fly:
//   tw[b, co, ci, kh, kw] = h_b * wv[idx] + bv[idx]     (HD = 1)
//
// Grid: (H/2, Cout/64, B). Block: 128 threads.
// CTA tile: 64 co x (2 rows x 64 cols). Thread tile: 8 co x 8 px.
// Inner loop uses packed fma.rn.f32x2 (FFMA2): accumulators hold co-pairs,
// weight pairs come contiguous from SMEM, x is stored duplicated (v,v) in
// SMEM so broadcast operands are a single LDS.64.
//
// mode 1: input = relu(bn_in(in)) fused at staging; epilogue = bn_out + relu
// mode 2: input raw;                                epilogue = + addsrc
// ---------------------------------------------------------------------------
__global__ __launch_bounds__(128, 2)
void hyperconv_kernel(const float* __restrict__ in,
                      float* __restrict__ out,
                      const float* __restrict__ wv,
                      const float* __restrict__ bv,
                      const float* __restrict__ hin,
                      const float* __restrict__ giA, const float* __restrict__ biA,
                      const float* __restrict__ miA, const float* __restrict__ viA,
                      const float* __restrict__ goB, const float* __restrict__ boB,
                      const float* __restrict__ moB, const float* __restrict__ voB,
                      const float* __restrict__ addsrc,
                      int mode)
{
    __shared__ __align__(16) float  Ws[72][64];        // [kk=ci*9+kh*3+kw][co]
    __shared__ __align__(16) float2 Xs[8][4][66];      // duplicated (v,v), halo cols
    __shared__ float sInv[CC];                         // fused input-BN scale
    __shared__ float sSh[CC];                          // fused input-BN shift

    const int h0  = blockIdx.x * 2;     // first of 2 output rows
    const int cot = blockIdx.y;         // 64-co tile, 0..3
    const int b   = blockIdx.z;         // sample

    const int tid = threadIdx.x;
    const int tm  = tid & 7;            // 8 threads across co
    const int tn  = tid >> 3;           // 16 threads across px
    const int tm8 = tm * 8;             // thread's first co (local)
    const int row = tn >> 3;            // 0/1 within the row pair
    const int c0  = (tn & 7) * 8;       // thread's first column

    const float hb = 0.5f + hin[b] * (1.0f / 64.0f);
    const int coBase = cot * 64;
    const float* inB = in + (size_t)b * CC * HH * WW;

    // Precompute fused input-BN coefficients once (mode 1 only).
    if (mode == 1) {
        for (int c = tid; c < CC; c += 128) {
            float inv = giA[c] * rsqrtf(viA[c] + 1e-5f);
            sInv[c] = inv;
            sSh[c]  = biA[c] - miA[c] * inv;
        }
    }
    // (first __syncthreads below covers this)

    unsigned long long acc[4][8];       // [co-pair][px]
    #pragma unroll
    for (int p = 0; p < 4; ++p)
        #pragma unroll
        for (int j = 0; j < 8; ++j)
            acc[p][j] = 0ull;

    const int co_l = tid >> 1;          // weight staging: one co per thread pair
    const int half = tid & 1;           // which 36-float half of the 72-k chunk

    for (int cc = 0; cc < CC / 8; ++cc) {
        const int ci0 = cc * 8;
        __syncthreads();                // also orders sInv/sSh on first iter

        // --- stage weights: Ws[kk][co] = hb * w + b
        {
            const int gco  = coBase + co_l;
            const int base = gco * K9 + ci0 * 9 + half * 36;   // 16B-aligned
            const float4* w4 = (const float4*)(wv + base);
            const float4* b4 = (const float4*)(bv + base);
            #pragma unroll
            for (int m = 0; m < 9; ++m) {
                float4 a  = w4[m];
                float4 c4 = b4[m];
                int kk = half * 36 + m * 4;
                Ws[kk + 0][co_l] = fmaf(hb, a.x, c4.x);
                Ws[kk + 1][co_l] = fmaf(hb, a.y, c4.y);
                Ws[kk + 2][co_l] = fmaf(hb, a.z, c4.z);
                Ws[kk + 3][co_l] = fmaf(hb, a.w, c4.w);
            }
        }

        // --- stage input: 8 ch x 4 rows (h0-1..h0+2) x 66 cols, duplicated
        for (int i = tid; i < 8 * 4 * 66; i += 128) {
            int ci  = i / 264;
            int rem = i - ci * 264;
            int r   = rem / 66;
            int cx  = rem - r * 66;
            int gr  = h0 + r - 1;
            int gc  = cx - 1;
            float v = 0.f;
            if ((unsigned)gr < HH && (unsigned)gc < WW)
                v = inB[((size_t)(ci0 + ci) * HH + gr) * WW + gc];
            if (mode == 1)
                v = fmaxf(fmaf(v, sInv[ci0 + ci], sSh[ci0 + ci]), 0.f);
            Xs[ci][r][cx] = make_float2(v, v);
        }
        __syncthreads();

        // --- compute: per (ci,kh): 10 LDS.64 + 6 LDS.128 + 96 FFMA2 (192 MACs)
        #pragma unroll 1
        for (int ci = 0; ci < 8; ++ci) {
            #pragma unroll
            for (int kh = 0; kh < 3; ++kh) {
                unsigned long long xd[10];
                const float2* xrow = &Xs[ci][row + kh][c0];
                #pragma unroll
                for (int c = 0; c < 10; ++c)
                    xd[c] = *(const unsigned long long*)&xrow[c];
                #pragma unroll
                for (int kw = 0; kw < 3; ++kw) {
                    const int kk = ci * 9 + kh * 3 + kw;
                    const ulonglong2 wA = *(const ulonglong2*)&Ws[kk][tm8];
                    const ulonglong2 wB = *(const ulonglong2*)&Ws[kk][tm8 + 4];
                    #pragma unroll
                    for (int j = 0; j < 8; ++j) {
                        acc[0][j] = ffma2(wA.x, xd[j + kw], acc[0][j]);
                        acc[1][j] = ffma2(wA.y, xd[j + kw], acc[1][j]);
                        acc[2][j] = ffma2(wB.x, xd[j + kw], acc[2][j]);
                        acc[3][j] = ffma2(wB.y, xd[j + kw], acc[3][j]);
                    }
                }
            }
        }
    }

    // --- epilogue: 8 co x 8 px per thread ---
    const int hrow = h0 + row;
    #pragma unroll
    for (int i = 0; i < 8; ++i) {
        const int p = i >> 1;
        const int gco = coBase + tm8 + i;
        float v[8];
        if (i & 1) {
            #pragma unroll
            for (int j = 0; j < 8; ++j) v[j] = hi32(acc[p][j]);
        } else {
            #pragma unroll
            for (int j = 0; j < 8; ++j) v[j] = lo32(acc[p][j]);
        }
        float* orow = out + (((size_t)b * CC + gco) * HH + hrow) * WW + c0;
        float4 r0, r1;
        if (mode == 1) {
            float inv = goB[gco] * rsqrtf(voB[gco] + 1e-5f);
            float sh  = boB[gco] - moB[gco] * inv;
            r0.x = fmaxf(fmaf(v[0], inv, sh), 0.f);
            r0.y = fmaxf(fmaf(v[1], inv, sh), 0.f);
            r0.z = fmaxf(fmaf(v[2], inv, sh), 0.f);
            r0.w = fmaxf(fmaf(v[3], inv, sh), 0.f);
            r1.x = fmaxf(fmaf(v[4], inv, sh), 0.f);
            r1.y = fmaxf(fmaf(v[5], inv, sh), 0.f);
            r1.z = fmaxf(fmaf(v[6], inv, sh), 0.f);
            r1.w = fmaxf(fmaf(v[7], inv, sh), 0.f);
        } else {
            const float* xr = addsrc + (((size_t)b * CC + gco) * HH + hrow) * WW + c0;
            float4 x0 = ((const float4*)xr)[0];
            float4 x1 = ((const float4*)xr)[1];
            r0.x = v[0] + x0.x;  r0.y = v[1] + x0.y;
            r0.z = v[2] + x0.z;  r0.w = v[3] + x0.w;
            r1.x = v[4] + x1.x;  r1.y = v[5] + x1.y;
            r1.z = v[6] + x1.z;  r1.w = v[7] + x1.w;
        }
        ((float4*)orow)[0] = r0;
        ((float4*)orow)[1] = r1;
    }
}

// ---------------------------------------------------------------------------
// kernel_launch — inputs in metadata order:
//  0:x 1:h_in 2:bn1_gamma 3:bn1_beta 4:bn1_mean 5:bn1_var 6:w1 7:b1
//  8:bn2_gamma 9:bn2_beta 10:bn2_mean 11:bn2_var 12:w2 13:b2
// ---------------------------------------------------------------------------
extern "C" void kernel_launch(void* const* d_in, const int* in_sizes, int n_in,
                              void* d_out, int out_size)
{
    const float* x    = (const float*)d_in[0];
    const float* hin  = (const float*)d_in[1];
    const float* g1   = (const float*)d_in[2];
    const float* be1  = (const float*)d_in[3];
    const float* mu1  = (const float*)d_in[4];
    const float* var1 = (const float*)d_in[5];
    const float* w1   = (const float*)d_in[6];
    const float* b1   = (const float*)d_in[7];
    const float* g2   = (const float*)d_in[8];
    const float* be2  = (const float*)d_in[9];
    const float* mu2  = (const float*)d_in[10];
    const float* var2 = (const float*)d_in[11];
    const float* w2   = (const float*)d_in[12];
    const float* b2   = (const float*)d_in[13];
    float* out = (float*)d_out;

    float* bufB = nullptr;
    cudaGetSymbolAddress((void**)&bufB, g_bufB);

    dim3 grid(HH / 2, CC / 64, BQ);    // (32 row-pairs, 4 co-tiles, 32 samples)

    // 1) conv1( relu(bn1(x)) ) + bn2 + relu -> bufB    (bn1 fused at staging)
    hyperconv_kernel<<<grid, 128>>>(x, bufB, w1, b1, hin,
                                    g1, be1, mu1, var1,
                                    g2, be2, mu2, var2,
                                    nullptr, 1);

    // 2) conv2(bufB) + residual(x) -> out
    hyperconv_kernel<<<grid, 128>>>(bufB, out, w2, b2, hin,
                                    g2, be2, mu2, var2,   // unused in mode 2
                                    g2, be2, mu2, var2,   // unused in mode 2
                                    x, 2);
}

// round 9
// speedup vs baseline: 2.4861x; 2.4861x over previous
#include <cuda_runtime.h>
#include <cuda_bf16.h>
#include <cstdint>

#define BQ 32
#define CC 256
#define HH 64
#define WW 64

// ---------------- static scratch ----------------
__device__ float g_bufB[(size_t)BQ*CC*HH*WW];
__device__ __nv_bfloat16 g_w1h[(size_t)BQ*9*CC*CC];
__device__ __nv_bfloat16 g_w1l[(size_t)BQ*9*CC*CC];
__device__ __nv_bfloat16 g_w2h[(size_t)BQ*9*CC*CC];
__device__ __nv_bfloat16 g_w2l[(size_t)BQ*9*CC*CC];

// ---------------- helpers ----------------
__device__ __forceinline__ uint32_t smem_u32(const void* p) {
    uint32_t a;
    asm("{ .reg .u64 t; cvta.to.shared.u64 t, %1; cvt.u32.u64 %0, t; }" : "=r"(a) : "l"(p));
    return a;
}

// hi = truncated top 16 bits (exact bf16), lo = rn(v - hi). Packs (va,vb), va in low half.
__device__ __forceinline__ void split2(float va, float vb, uint32_t& hp, uint32_t& lp) {
    uint32_t ba = __float_as_uint(va), bb = __float_as_uint(vb);
    hp = __byte_perm(ba, bb, 0x7632);
    float la = va - __uint_as_float(ba & 0xFFFF0000u);
    float lb = vb - __uint_as_float(bb & 0xFFFF0000u);
    asm("cvt.rn.bf16x2.f32 %0, %1, %2;" : "=r"(lp) : "f"(lb), "f"(la));
}

__device__ __forceinline__ void ldsm4(uint32_t* r, uint32_t addr) {
    asm volatile("ldmatrix.sync.aligned.m8n8.x4.shared.b16 {%0,%1,%2,%3}, [%4];"
                 : "=r"(r[0]), "=r"(r[1]), "=r"(r[2]), "=r"(r[3]) : "r"(addr));
}
__device__ __forceinline__ void mma16816(float* d, const uint32_t* a, const uint32_t* b) {
    asm volatile("mma.sync.aligned.m16n8k16.row.col.f32.bf16.bf16.f32 "
                 "{%0,%1,%2,%3}, {%4,%5,%6,%7}, {%8,%9}, {%0,%1,%2,%3};"
                 : "+f"(d[0]), "+f"(d[1]), "+f"(d[2]), "+f"(d[3])
                 : "r"(a[0]), "r"(a[1]), "r"(a[2]), "r"(a[3]), "r"(b[0]), "r"(b[1]));
}
#define CP16(dst, src) asm volatile("cp.async.cg.shared.global [%0], [%1], 16;" :: "r"(dst), "l"(src))
#define CP_COMMIT()    asm volatile("cp.async.commit_group;" ::: "memory")
#define CP_WAIT0()     asm volatile("cp.async.wait_group 0;" ::: "memory")

// ---------------- presynth: tw[b][khw][co][ci] = hb*w + bias, bf16 hi/lo ----
__global__ __launch_bounds__(288)
void presynth_kernel(const float* __restrict__ wv, const float* __restrict__ bv,
                     const float* __restrict__ hin,
                     __nv_bfloat16* __restrict__ oh, __nv_bfloat16* __restrict__ ol)
{
    __shared__ float sw[9*256];
    __shared__ float sbb[9*256];
    __shared__ float shb[8];
    const int co  = blockIdx.x;
    const int bg  = blockIdx.y;
    const int tid = threadIdx.x;

    for (int t = tid; t < 2304; t += 288) {
        int ciL = t / 9, khw = t - ciL * 9;
        sw[khw*256 + ciL]  = wv[co*2304 + t];
        sbb[khw*256 + ciL] = bv[co*2304 + t];
    }
    if (tid < 8) shb[tid] = 0.5f + hin[bg*8 + tid] * (1.0f/64.0f);
    __syncthreads();

    #pragma unroll 1
    for (int bi = 0; bi < 8; ++bi) {
        const int b = bg*8 + bi;
        const float hb = shb[bi];
        #pragma unroll
        for (int r = 0; r < 2; ++r) {
            int item = tid + r*288;            // 576 = 9 khw x 64 ci-quads
            int khw = item >> 6;
            int ci  = (item & 63) * 4;
            float4 w4 = *(const float4*)&sw[khw*256 + ci];
            float4 b4 = *(const float4*)&sbb[khw*256 + ci];
            float v0 = fmaf(hb, w4.x, b4.x);
            float v1 = fmaf(hb, w4.y, b4.y);
            float v2 = fmaf(hb, w4.z, b4.z);
            float v3 = fmaf(hb, w4.w, b4.w);
            uint32_t h0,l0,h1,l1;
            split2(v0, v1, h0, l0);
            split2(v2, v3, h1, l1);
            size_t o = (((size_t)b*9 + khw)*256 + co)*256 + ci;
            *(uint2*)(oh + o) = make_uint2(h0, h1);
            *(uint2*)(ol + o) = make_uint2(l0, l1);
        }
    }
}

// ---------------- mma.sync implicit-GEMM hyperconv ----------------
// CTA: 512 thr, tile M=128 co x N=128 px (2 rows x 64 cols), K-chunk 64.
// SMEM rows padded to 144 B for conflict-free ldmatrix.
#define SROWB 144
#define AHI_O 0
#define ALO_O 18432
#define BHI_O 36864
#define BLO_O 55296
#define BUFSZ 73728
#define OFF_INV 0
#define OFF_SH  1024
#define OFF_BUF 2048
#define SMEM_TOT (OFF_BUF + 2*BUFSZ)     // 149504 B

__global__ __launch_bounds__(512, 1)
void hyperconv_mma(const float* __restrict__ in,
                   float* __restrict__ out,
                   const __nv_bfloat16* __restrict__ wh,
                   const __nv_bfloat16* __restrict__ wl,
                   const float* __restrict__ giA, const float* __restrict__ biA,
                   const float* __restrict__ miA, const float* __restrict__ viA,
                   const float* __restrict__ goB, const float* __restrict__ boB,
                   const float* __restrict__ moB, const float* __restrict__ voB,
                   const float* __restrict__ addsrc,
                   int mode)
{
    extern __shared__ __align__(1024) char smem[];
    const uint32_t sbase = smem_u32(smem);

    const int tid  = threadIdx.x;
    const int wid  = tid >> 5;
    const int lane = tid & 31;
    const int h0     = blockIdx.x * 2;
    const int coBase = blockIdx.y * 128;
    const int b      = blockIdx.z;

    float* sInv = (float*)(smem + OFF_INV);
    float* sSh  = (float*)(smem + OFF_SH);
    if (mode == 1) {
        for (int c = tid; c < CC; c += 512) {
            float inv = giA[c] * rsqrtf(viA[c] + 1e-5f);
            sInv[c] = inv;
            sSh[c]  = biA[c] - miA[c] * inv;
        }
    }
    __syncthreads();

    const float* inB = in + (size_t)b * CC * HH * WW;

    // staging coordinates
    const int am = tid >> 2;            // A row (co local) 0..127
    const int aq = (tid & 3) * 2;       // which pair of 16B chunks
    const int px = tid & 127;           // B row (pixel) 0..127
    const int qh = tid >> 7;            // 0..3 : 16-ci block
    const int pr = px >> 6;             // pixel row in tile
    const int pw = px & 63;             // pixel col

    // compute coordinates
    const int wm = wid & 3;             // M warp 0..3 (32 co each)
    const int wn = wid >> 2;            // N warp 0..3 (32 px each)
    const int aRow = (wm*32 + (lane & 15)) * SROWB + ((lane >> 4) << 4);
    const int bRow = (wn*32 + (lane & 7) + ((lane >> 4) << 3)) * SROWB
                   + (((lane >> 3) & 1) << 4);

    float acc[2][4][4];
    #pragma unroll
    for (int i = 0; i < 2; ++i)
        #pragma unroll
        for (int j = 0; j < 4; ++j)
            #pragma unroll
            for (int k = 0; k < 4; ++k)
                acc[i][j][k] = 0.f;

    float bv[16];

    auto stageA = [&](int c, int buf) {
        const int khw = c >> 2, ci0 = (c & 3) << 6;
        const size_t rowbase =
            (((size_t)b * 9 + khw) * 256 + coBase + am) * 256 + ci0;
        const char* srcH = (const char*)(wh + rowbase) + aq * 16;
        const char* srcL = (const char*)(wl + rowbase) + aq * 16;
        const uint32_t dstH = sbase + OFF_BUF + buf*BUFSZ + AHI_O + am*SROWB + aq*16;
        const uint32_t dstL = dstH + (ALO_O - AHI_O);
        CP16(dstH,      srcH);
        CP16(dstH + 16, srcH + 16);
        CP16(dstL,      srcL);
        CP16(dstL + 16, srcL + 16);
        CP_COMMIT();
    };

    auto loadB = [&](int c) {
        const int khw = c >> 2, ci0 = (c & 3) << 6;
        const int dh = khw / 3 - 1;
        const int dw = khw - (khw / 3) * 3 - 1;
        const int hh = h0 + pr + dh;
        const int wp = pw + dw;
        const bool valid = ((unsigned)hh < HH) && ((unsigned)wp < WW);
        const int cb = ci0 + qh * 16;
        const float* src = inB + (size_t)cb * (HH*WW) + hh * WW + wp;
        #pragma unroll
        for (int i = 0; i < 16; ++i) {
            float v = 0.f;
            if (valid) {
                v = src[(size_t)i * (HH*WW)];
                if (mode == 1) {
                    const int ci = cb + i;
                    v = fmaxf(fmaf(v, sInv[ci], sSh[ci]), 0.f);
                }
            }
            bv[i] = v;
        }
    };

    auto storeB = [&](int buf) {
        uint32_t hp[8], lp[8];
        #pragma unroll
        for (int i = 0; i < 8; ++i)
            split2(bv[2*i], bv[2*i+1], hp[i], lp[i]);
        char* dh = smem + OFF_BUF + buf*BUFSZ + BHI_O + px*SROWB + qh*32;
        char* dl = dh + (BLO_O - BHI_O);
        *(uint4*)(dh)      = make_uint4(hp[0], hp[1], hp[2], hp[3]);
        *(uint4*)(dh + 16) = make_uint4(hp[4], hp[5], hp[6], hp[7]);
        *(uint4*)(dl)      = make_uint4(lp[0], lp[1], lp[2], lp[3]);
        *(uint4*)(dl + 16) = make_uint4(lp[4], lp[5], lp[6], lp[7]);
    };

    auto compute = [&](int buf) {
        const uint32_t base = sbase + OFF_BUF + buf*BUFSZ;
        #pragma unroll
        for (int s = 0; s < 4; ++s) {
            uint32_t ah[2][4], al[2][4], bh[2][4], bl[2][4];
            #pragma unroll
            for (int mi = 0; mi < 2; ++mi) {
                const uint32_t ao = base + aRow + mi*(16*SROWB) + s*32;
                ldsm4(ah[mi], ao + AHI_O);
                ldsm4(al[mi], ao + ALO_O);
            }
            #pragma unroll
            for (int nj = 0; nj < 2; ++nj) {
                const uint32_t bo = base + bRow + nj*(16*SROWB) + s*32;
                ldsm4(bh[nj], bo + BHI_O);      // non-trans: smem is [n][k]
                ldsm4(bl[nj], bo + BLO_O);
            }
            #pragma unroll
            for (int mi = 0; mi < 2; ++mi)
                #pragma unroll
                for (int nf = 0; nf < 4; ++nf) {
                    const uint32_t* bhp = &bh[nf >> 1][(nf & 1) * 2];
                    const uint32_t* blp = &bl[nf >> 1][(nf & 1) * 2];
                    mma16816(acc[mi][nf], ah[mi], bhp);   // Ah*Bh
                    mma16816(acc[mi][nf], ah[mi], blp);   // Ah*Bl
                    mma16816(acc[mi][nf], al[mi], bhp);   // Al*Bh
                }
        }
    };

    // pipeline: stage(0) -> [ prefetch(c+1) | compute(c) | store(c+1) ]
    stageA(0, 0);
    loadB(0);
    storeB(0);
    CP_WAIT0();
    __syncthreads();

    for (int c = 0; c < 36; ++c) {
        const int buf = c & 1;
        if (c < 35) {
            stageA(c + 1, buf ^ 1);
            loadB(c + 1);
        }
        compute(buf);
        if (c < 35) storeB(buf ^ 1);
        CP_WAIT0();
        __syncthreads();
    }

    // ---------------- epilogue ----------------
    const int g  = lane >> 2;
    const int qt = lane & 3;
    #pragma unroll
    for (int mi = 0; mi < 2; ++mi) {
        #pragma unroll
        for (int rh = 0; rh < 2; ++rh) {
            const int m   = wm*32 + mi*16 + rh*8 + g;
            const int gco = coBase + m;
            float inv = 0.f, sh = 0.f;
            if (mode == 1) {
                inv = goB[gco] * rsqrtf(voB[gco] + 1e-5f);
                sh  = boB[gco] - moB[gco] * inv;
            }
            #pragma unroll
            for (int nf = 0; nf < 4; ++nf) {
                const int n = wn*32 + (nf >> 1)*16 + (nf & 1)*8 + qt*2;
                const int h = h0 + (n >> 6);
                const int w = n & 63;
                const size_t idx = (((size_t)b*CC + gco)*HH + h)*WW + w;
                float v0 = acc[mi][nf][rh*2 + 0];
                float v1 = acc[mi][nf][rh*2 + 1];
                float2 o;
                if (mode == 1) {
                    o.x = fmaxf(fmaf(v0, inv, sh), 0.f);
                    o.y = fmaxf(fmaf(v1, inv, sh), 0.f);
                } else {
                    float2 xv = *(const float2*)(addsrc + idx);
                    o.x = v0 + xv.x;
                    o.y = v1 + xv.y;
                }
                *(float2*)(out + idx) = o;
            }
        }
    }
}

// ---------------- launcher ----------------
extern "C" void kernel_launch(void* const* d_in, const int* in_sizes, int n_in,
                              void* d_out, int out_size)
{
    const float* x    = (const float*)d_in[0];
    const float* hin  = (const float*)d_in[1];
    const float* g1   = (const float*)d_in[2];
    const float* be1  = (const float*)d_in[3];
    const float* mu1  = (const float*)d_in[4];
    const float* var1 = (const float*)d_in[5];
    const float* w1   = (const float*)d_in[6];
    const float* b1   = (const float*)d_in[7];
    const float* g2   = (const float*)d_in[8];
    const float* be2  = (const float*)d_in[9];
    const float* mu2  = (const float*)d_in[10];
    const float* var2 = (const float*)d_in[11];
    const float* w2   = (const float*)d_in[12];
    const float* b2   = (const float*)d_in[13];
    float* out = (float*)d_out;

    float* bufB = nullptr;
    __nv_bfloat16 *w1h, *w1l, *w2h, *w2l;
    cudaGetSymbolAddress((void**)&bufB, g_bufB);
    cudaGetSymbolAddress((void**)&w1h, g_w1h);
    cudaGetSymbolAddress((void**)&w1l, g_w1l);
    cudaGetSymbolAddress((void**)&w2h, g_w2h);
    cudaGetSymbolAddress((void**)&w2l, g_w2l);

    cudaFuncSetAttribute(hyperconv_mma,
                         cudaFuncAttributeMaxDynamicSharedMemorySize, SMEM_TOT);

    dim3 pgrid(256, 4);
    presynth_kernel<<<pgrid, 288>>>(w1, b1, hin, w1h, w1l);
    presynth_kernel<<<pgrid, 288>>>(w2, b2, hin, w2h, w2l);

    dim3 grid(32, 2, BQ);   // (32 px-tiles of 2 rows, 2 co-tiles, 32 samples)

    hyperconv_mma<<<grid, 512, SMEM_TOT>>>(x, bufB, w1h, w1l,
                                           g1, be1, mu1, var1,
                                           g2, be2, mu2, var2,
                                           nullptr, 1);

    hyperconv_mma<<<grid, 512, SMEM_TOT>>>(bufB, out, w2h, w2l,
                                           g2, be2, mu2, var2,
                                           g2, be2, mu2, var2,
                                           x, 2);
}